// round 1
// baseline (speedup 1.0000x reference)
#include <cuda_runtime.h>

#define DIM    1024
#define HEADS  16
#define GROUPS 4
#define HG     (HEADS/GROUPS)
#define DHEAD  64
#define INNER  1024
#define KVDIM  512
#define BATCH  4
#define SEQ    2048
#define ROWS   (BATCH*SEQ)
#define LN_EPS 1e-6f

// Scratch (allocation-free: __device__ globals)
__device__ __align__(16) float g_xn[ROWS*DIM];    // 32 MB
__device__ __align__(16) float g_q [ROWS*INNER];  // 32 MB
__device__ __align__(16) float g_kv[ROWS*KVDIM];  // 16 MB
__device__ __align__(16) float g_o [ROWS*INNER];  // 32 MB

// ---------------- input layernorm over DIM=1024 ----------------
__global__ __launch_bounds__(256) void ln_kernel(const float* __restrict__ x,
                                                 const float* __restrict__ sc,
                                                 const float* __restrict__ bi) {
    int row = blockIdx.x;
    int t = threadIdx.x;
    const float4 a = reinterpret_cast<const float4*>(x)[row*(DIM/4) + t];
    float s  = a.x + a.y + a.z + a.w;
    float sq = a.x*a.x + a.y*a.y + a.z*a.z + a.w*a.w;
    #pragma unroll
    for (int o = 16; o > 0; o >>= 1) {
        s  += __shfl_xor_sync(0xffffffffu, s,  o);
        sq += __shfl_xor_sync(0xffffffffu, sq, o);
    }
    __shared__ float ws[8], wq[8];
    if ((t & 31) == 0) { ws[t >> 5] = s; wq[t >> 5] = sq; }
    __syncthreads();
    s = 0.f; sq = 0.f;
    #pragma unroll
    for (int i = 0; i < 8; i++) { s += ws[i]; sq += wq[i]; }
    float mean = s  * (1.f/DIM);
    float var  = sq * (1.f/DIM) - mean*mean;
    float rstd = rsqrtf(var + LN_EPS);
    float4 s4 = reinterpret_cast<const float4*>(sc)[t];
    float4 b4 = reinterpret_cast<const float4*>(bi)[t];
    float4 o4;
    o4.x = (a.x - mean)*rstd*s4.x + b4.x;
    o4.y = (a.y - mean)*rstd*s4.y + b4.y;
    o4.z = (a.z - mean)*rstd*s4.z + b4.z;
    o4.w = (a.w - mean)*rstd*s4.w + b4.w;
    reinterpret_cast<float4*>(g_xn)[row*(DIM/4) + t] = o4;
}

// ---------------- generic fp32 GEMM: C[M,Ncols] = A[M,K] @ W[K,Ncols] ----------------
// BM=128, BN=128, BK=8, 256 threads, 8x8 micro-tile per thread.
__global__ __launch_bounds__(256) void gemm_kernel(const float* __restrict__ A,
                                                   const float* __restrict__ W,
                                                   float* __restrict__ C,
                                                   int Ncols, int K) {
    __shared__ float As[8][128];
    __shared__ float Bs[8][128];
    const int bm = blockIdx.y * 128;
    const int bn = blockIdx.x * 128;
    const int tid = threadIdx.x;
    const int tx = tid & 15;
    const int ty = tid >> 4;
    const int ar = tid >> 1, ac = (tid & 1) * 4;  // A: one float4 per thread
    const int br = tid >> 5, bc = (tid & 31) * 4; // B: one float4 per thread
    const float* Ap = A + (size_t)(bm + ar) * K + ac;
    const float* Wp = W + (size_t)br * Ncols + bn + bc;
    float acc[8][8];
    #pragma unroll
    for (int i = 0; i < 8; i++)
        #pragma unroll
        for (int j = 0; j < 8; j++) acc[i][j] = 0.f;

    for (int k0 = 0; k0 < K; k0 += 8) {
        float4 a4 = *reinterpret_cast<const float4*>(Ap); Ap += 8;
        float4 b4 = *reinterpret_cast<const float4*>(Wp); Wp += (size_t)8 * Ncols;
        __syncthreads();
        As[ac+0][ar] = a4.x; As[ac+1][ar] = a4.y;
        As[ac+2][ar] = a4.z; As[ac+3][ar] = a4.w;
        *reinterpret_cast<float4*>(&Bs[br][bc]) = b4;
        __syncthreads();
        #pragma unroll
        for (int kk = 0; kk < 8; kk++) {
            float av[8], bv[8];
            #pragma unroll
            for (int i = 0; i < 8; i++) av[i] = As[kk][ty*8 + i];
            #pragma unroll
            for (int j = 0; j < 8; j++) bv[j] = Bs[kk][tx*8 + j];
            #pragma unroll
            for (int i = 0; i < 8; i++)
                #pragma unroll
                for (int j = 0; j < 8; j++)
                    acc[i][j] += av[i] * bv[j];
        }
    }
    #pragma unroll
    for (int i = 0; i < 8; i++) {
        float* cp = C + (size_t)(bm + ty*8 + i) * Ncols + bn + tx*8;
        *reinterpret_cast<float4*>(cp)     = make_float4(acc[i][0], acc[i][1], acc[i][2], acc[i][3]);
        *reinterpret_cast<float4*>(cp + 4) = make_float4(acc[i][4], acc[i][5], acc[i][6], acc[i][7]);
    }
}

// ---------------- per-head LN on q (16 heads) and k (4 groups), over Dh=64 ----------------
// One warp per 64-vector. Folds attention scale (1/8) into q.
__global__ __launch_bounds__(128) void qkln_kernel(const float* __restrict__ qs,
                                                   const float* __restrict__ qb,
                                                   const float* __restrict__ ks,
                                                   const float* __restrict__ kb) {
    int row  = blockIdx.x;                              // 0..ROWS-1
    int unit = blockIdx.y * 4 + (threadIdx.x >> 5);     // 0..19
    int lane = threadIdx.x & 31;
    float* p;
    const float *sc, *bi;
    float postmul;
    if (unit < HEADS) {
        p = g_q + (size_t)row * INNER + unit * 64;
        sc = qs; bi = qb; postmul = 0.125f;             // fold Dh^-0.5
    } else {
        p = g_kv + (size_t)row * KVDIM + (unit - HEADS) * 64;
        sc = ks; bi = kb; postmul = 1.0f;
    }
    float v0 = p[lane], v1 = p[lane + 32];
    float s  = v0 + v1;
    float sq = v0*v0 + v1*v1;
    #pragma unroll
    for (int o = 16; o > 0; o >>= 1) {
        s  += __shfl_xor_sync(0xffffffffu, s,  o);
        sq += __shfl_xor_sync(0xffffffffu, sq, o);
    }
    float mean = s  * (1.f/64.f);
    float var  = sq * (1.f/64.f) - mean*mean;
    float rstd = rsqrtf(var + LN_EPS);
    p[lane]      = ((v0 - mean)*rstd*sc[lane]      + bi[lane]     ) * postmul;
    p[lane + 32] = ((v1 - mean)*rstd*sc[lane + 32] + bi[lane + 32]) * postmul;
}

// ---------------- flash attention: 1 thread = 1 q row ----------------
// grid = (B*H, SEQ/128), block = 128. K/V streamed in 32x64 tiles through SMEM.
__global__ __launch_bounds__(128) void attn_kernel() {
    __shared__ float Ks[32][64];
    __shared__ float Vs[32][64];
    const int bh = blockIdx.x;
    const int b  = bh / HEADS;
    const int h  = bh % HEADS;
    const int g  = h / HG;
    const int n  = blockIdx.y * 128 + threadIdx.x;

    const float* qp = g_q + (size_t)(b*SEQ + n) * INNER + h * 64;
    float q[64];
    #pragma unroll
    for (int i = 0; i < 16; i++) {
        float4 t = *reinterpret_cast<const float4*>(qp + 4*i);
        q[4*i+0] = t.x; q[4*i+1] = t.y; q[4*i+2] = t.z; q[4*i+3] = t.w;
    }
    float m = -1e30f, l = 0.f;
    float o[64];
    #pragma unroll
    for (int d = 0; d < 64; d++) o[d] = 0.f;

    const float* kbase = g_kv + (size_t)b * SEQ * KVDIM + g * 64;

    for (int t0 = 0; t0 < SEQ; t0 += 32) {
        __syncthreads();
        #pragma unroll
        for (int p = 0; p < 4; p++) {
            int idx = p * 128 + threadIdx.x;   // 0..511
            int j = idx >> 4, c = (idx & 15) * 4;
            const float* kr = kbase + (size_t)(t0 + j) * KVDIM + c;
            *reinterpret_cast<float4*>(&Ks[j][c]) = *reinterpret_cast<const float4*>(kr);
            *reinterpret_cast<float4*>(&Vs[j][c]) = *reinterpret_cast<const float4*>(kr + 256);
        }
        __syncthreads();

        float s[32];
        #pragma unroll
        for (int j = 0; j < 32; j++) {
            float acc = 0.f;
            #pragma unroll
            for (int d = 0; d < 64; d++) acc += q[d] * Ks[j][d];
            s[j] = acc;
        }
        float mt = m;
        #pragma unroll
        for (int j = 0; j < 32; j++) mt = fmaxf(mt, s[j]);
        float alpha = __expf(m - mt);
        m = mt;
        l *= alpha;
        #pragma unroll
        for (int d = 0; d < 64; d++) o[d] *= alpha;
        #pragma unroll
        for (int j = 0; j < 32; j++) {
            float pj = __expf(s[j] - mt);
            l += pj;
            #pragma unroll
            for (int d = 0; d < 64; d++) o[d] += pj * Vs[j][d];
        }
    }

    float inv = 1.f / l;
    float* op = g_o + (size_t)(b*SEQ + n) * INNER + h * 64;
    #pragma unroll
    for (int i = 0; i < 16; i++) {
        float4 v = make_float4(o[4*i+0]*inv, o[4*i+1]*inv, o[4*i+2]*inv, o[4*i+3]*inv);
        *reinterpret_cast<float4*>(op + 4*i) = v;
    }
}

extern "C" void kernel_launch(void* const* d_in, const int* in_sizes, int n_in,
                              void* d_out, int out_size) {
    const float* x    = (const float*)d_in[0];
    const float* lns  = (const float*)d_in[1];
    const float* lnb  = (const float*)d_in[2];
    const float* Wq   = (const float*)d_in[3];
    const float* Wkv  = (const float*)d_in[4];
    const float* qns  = (const float*)d_in[5];
    const float* qnb  = (const float*)d_in[6];
    const float* kns  = (const float*)d_in[7];
    const float* knb  = (const float*)d_in[8];
    const float* Wout = (const float*)d_in[9];
    float* out = (float*)d_out;

    void *pxn, *pq, *pkv, *po;
    cudaGetSymbolAddress(&pxn, g_xn);
    cudaGetSymbolAddress(&pq,  g_q);
    cudaGetSymbolAddress(&pkv, g_kv);
    cudaGetSymbolAddress(&po,  g_o);

    ln_kernel<<<ROWS, 256>>>(x, lns, lnb);
    gemm_kernel<<<dim3(INNER/128, ROWS/128), 256>>>((const float*)pxn, Wq,  (float*)pq,  INNER, DIM);
    gemm_kernel<<<dim3(KVDIM/128, ROWS/128), 256>>>((const float*)pxn, Wkv, (float*)pkv, KVDIM, DIM);
    qkln_kernel<<<dim3(ROWS, 5), 128>>>(qns, qnb, kns, knb);
    attn_kernel<<<dim3(BATCH*HEADS, SEQ/128), 128>>>();
    gemm_kernel<<<dim3(DIM/128, ROWS/128), 256>>>((const float*)po, Wout, out, DIM, INNER);
}

// round 4
// speedup vs baseline: 3.0902x; 3.0902x over previous
#include <cuda_runtime.h>
#include <cuda_bf16.h>
#include <cstdint>

#define DIM    1024
#define HEADS  16
#define GROUPS 4
#define HG     (HEADS/GROUPS)
#define DHEAD  64
#define INNER  1024
#define KVDIM  512
#define BATCH  4
#define SEQ    2048
#define ROWS   (BATCH*SEQ)
#define LN_EPS 1e-6f
#define LOG2E  1.44269504088896f

// ---------------- scratch (__device__ globals, allocation-free) ----------------
__device__ __align__(16) __nv_bfloat16 g_xn_hi[ROWS*DIM];
__device__ __align__(16) __nv_bfloat16 g_xn_lo[ROWS*DIM];
__device__ __align__(16) float         g_q [ROWS*INNER];
__device__ __align__(16) float         g_kv[ROWS*KVDIM];
__device__ __align__(16) __nv_bfloat16 g_qh[ROWS*INNER];
__device__ __align__(16) __nv_bfloat16 g_ql[ROWS*INNER];
__device__ __align__(16) __nv_bfloat16 g_kh[BATCH*GROUPS*SEQ*DHEAD];
__device__ __align__(16) __nv_bfloat16 g_kl[BATCH*GROUPS*SEQ*DHEAD];
__device__ __align__(16) __nv_bfloat16 g_vth[BATCH*GROUPS*DHEAD*SEQ];  // [bg][d][n]
__device__ __align__(16) __nv_bfloat16 g_vtl[BATCH*GROUPS*DHEAD*SEQ];
__device__ __align__(16) __nv_bfloat16 g_oh[ROWS*INNER];
__device__ __align__(16) __nv_bfloat16 g_ol[ROWS*INNER];
__device__ __align__(16) __nv_bfloat16 g_wq_hi [INNER*DIM];   // [N,K]
__device__ __align__(16) __nv_bfloat16 g_wq_lo [INNER*DIM];
__device__ __align__(16) __nv_bfloat16 g_wkv_hi[KVDIM*DIM];
__device__ __align__(16) __nv_bfloat16 g_wkv_lo[KVDIM*DIM];
__device__ __align__(16) __nv_bfloat16 g_wo_hi [DIM*INNER];
__device__ __align__(16) __nv_bfloat16 g_wo_lo [DIM*INNER];

// ---------------- helpers ----------------
__device__ __forceinline__ void mma_bf16(float c[4], const uint32_t a[4],
                                         uint32_t b0, uint32_t b1) {
    asm volatile(
        "mma.sync.aligned.m16n8k16.row.col.f32.bf16.bf16.f32 "
        "{%0,%1,%2,%3}, {%4,%5,%6,%7}, {%8,%9}, {%0,%1,%2,%3};"
        : "+f"(c[0]), "+f"(c[1]), "+f"(c[2]), "+f"(c[3])
        : "r"(a[0]), "r"(a[1]), "r"(a[2]), "r"(a[3]), "r"(b0), "r"(b1));
}
__device__ __forceinline__ void split_bf16(float v, __nv_bfloat16& h, __nv_bfloat16& l) {
    h = __float2bfloat16(v);
    l = __float2bfloat16(v - __bfloat162float(h));
}
__device__ __forceinline__ uint32_t pack2_u32(__nv_bfloat16 a, __nv_bfloat16 b) {
    __nv_bfloat162 p(a, b);
    return *reinterpret_cast<uint32_t*>(&p);
}
// split two fp32 into packed bf16x2 hi and lo words
__device__ __forceinline__ void split_pack2(float v0, float v1, uint32_t& hw, uint32_t& lw) {
    __nv_bfloat16 h0, l0, h1, l1;
    split_bf16(v0, h0, l0);
    split_bf16(v1, h1, l1);
    hw = pack2_u32(h0, h1);
    lw = pack2_u32(l0, l1);
}

// ---------------- input layernorm, emits bf16 hi/lo split ----------------
__global__ __launch_bounds__(256) void ln_kernel(const float* __restrict__ x,
                                                 const float* __restrict__ sc,
                                                 const float* __restrict__ bi) {
    int row = blockIdx.x;
    int t = threadIdx.x;
    const float4 a = reinterpret_cast<const float4*>(x)[row*(DIM/4) + t];
    float s  = a.x + a.y + a.z + a.w;
    float sq = a.x*a.x + a.y*a.y + a.z*a.z + a.w*a.w;
    #pragma unroll
    for (int o = 16; o > 0; o >>= 1) {
        s  += __shfl_xor_sync(0xffffffffu, s,  o);
        sq += __shfl_xor_sync(0xffffffffu, sq, o);
    }
    __shared__ float ws[8], wq[8];
    if ((t & 31) == 0) { ws[t >> 5] = s; wq[t >> 5] = sq; }
    __syncthreads();
    s = 0.f; sq = 0.f;
    #pragma unroll
    for (int i = 0; i < 8; i++) { s += ws[i]; sq += wq[i]; }
    float mean = s  * (1.f/DIM);
    float var  = sq * (1.f/DIM) - mean*mean;
    float rstd = rsqrtf(var + LN_EPS);
    float4 s4 = reinterpret_cast<const float4*>(sc)[t];
    float4 b4 = reinterpret_cast<const float4*>(bi)[t];
    float v[4];
    v[0] = (a.x - mean)*rstd*s4.x + b4.x;
    v[1] = (a.y - mean)*rstd*s4.y + b4.y;
    v[2] = (a.z - mean)*rstd*s4.z + b4.z;
    v[3] = (a.w - mean)*rstd*s4.w + b4.w;
    __nv_bfloat16 hi[4], lo[4];
    #pragma unroll
    for (int i = 0; i < 4; i++) split_bf16(v[i], hi[i], lo[i]);
    size_t base = (size_t)row * DIM + t * 4;
    *reinterpret_cast<__nv_bfloat162*>(g_xn_hi + base)     = __nv_bfloat162(hi[0], hi[1]);
    *reinterpret_cast<__nv_bfloat162*>(g_xn_hi + base + 2) = __nv_bfloat162(hi[2], hi[3]);
    *reinterpret_cast<__nv_bfloat162*>(g_xn_lo + base)     = __nv_bfloat162(lo[0], lo[1]);
    *reinterpret_cast<__nv_bfloat162*>(g_xn_lo + base + 2) = __nv_bfloat162(lo[2], lo[3]);
}

// ---------------- weight transpose + split: W[K,N] fp32 -> T[N,K] bf16 hi/lo ----------------
__global__ __launch_bounds__(256) void wconv_kernel(const float* __restrict__ W,
                                                    __nv_bfloat16* __restrict__ Thi,
                                                    __nv_bfloat16* __restrict__ Tlo,
                                                    int K, int N) {
    __shared__ float tile[32][33];
    int kb = blockIdx.y * 32, nb = blockIdx.x * 32;
    int tx = threadIdx.x & 31, ty = threadIdx.x >> 5;  // 32 x 8
    #pragma unroll
    for (int i = ty; i < 32; i += 8)
        tile[i][tx] = W[(size_t)(kb + i) * N + nb + tx];
    __syncthreads();
    #pragma unroll
    for (int i = ty; i < 32; i += 8) {
        float v = tile[tx][i];
        __nv_bfloat16 h, l;
        split_bf16(v, h, l);
        size_t idx = (size_t)(nb + i) * K + kb + tx;
        Thi[idx] = h;
        Tlo[idx] = l;
    }
}

// ---------------- warp-MMA split-bf16 GEMM: C[M,N] = A[M,K] @ T[N,K]^T ----------------
// Block tile 128x128, KC=32 per SMEM chunk, 8 warps (4m x 2n), warp tile 32x64.
#define KC 32
__global__ __launch_bounds__(256) void gemm_mma(const __nv_bfloat16* __restrict__ Ahi,
                                                const __nv_bfloat16* __restrict__ Alo,
                                                const __nv_bfloat16* __restrict__ Bhi,
                                                const __nv_bfloat16* __restrict__ Blo,
                                                float* __restrict__ C, int N, int K) {
    __shared__ __nv_bfloat16 Ah[128][40], Al[128][40], Bh[128][40], Bl[128][40];
    const int tid  = threadIdx.x;
    const int warp = tid >> 5, lane = tid & 31;
    const int wm = warp & 3, wn = warp >> 2;       // 4 x 2
    const int gi = lane >> 2, t = lane & 3;
    const int bm = blockIdx.y * 128;
    const int bn = blockIdx.x * 128;

    float acc[2][8][4];
    #pragma unroll
    for (int mf = 0; mf < 2; mf++)
        #pragma unroll
        for (int nf = 0; nf < 8; nf++)
            #pragma unroll
            for (int i = 0; i < 4; i++) acc[mf][nf][i] = 0.f;

    for (int it = 0; it < K / KC; it++) {
        const int k0 = it * KC;
        __syncthreads();
        #pragma unroll
        for (int ch = tid; ch < 512; ch += 256) {
            int r = ch >> 2, c = ch & 3;    // 4 x 16B chunks per 64B row
            const uint4* pa_h = reinterpret_cast<const uint4*>(Ahi + (size_t)(bm + r) * K + k0) + c;
            const uint4* pa_l = reinterpret_cast<const uint4*>(Alo + (size_t)(bm + r) * K + k0) + c;
            const uint4* pb_h = reinterpret_cast<const uint4*>(Bhi + (size_t)(bn + r) * K + k0) + c;
            const uint4* pb_l = reinterpret_cast<const uint4*>(Blo + (size_t)(bn + r) * K + k0) + c;
            *reinterpret_cast<uint4*>(&Ah[r][c*8]) = *pa_h;
            *reinterpret_cast<uint4*>(&Al[r][c*8]) = *pa_l;
            *reinterpret_cast<uint4*>(&Bh[r][c*8]) = *pb_h;
            *reinterpret_cast<uint4*>(&Bl[r][c*8]) = *pb_l;
        }
        __syncthreads();
        #pragma unroll
        for (int ks = 0; ks < 2; ks++) {
            const int kc = ks * 16 + 2 * t;
            uint32_t ah[2][4], al[2][4];
            #pragma unroll
            for (int mf = 0; mf < 2; mf++) {
                int rr = wm * 32 + mf * 16;
                ah[mf][0] = *reinterpret_cast<const uint32_t*>(&Ah[rr + gi    ][kc]);
                ah[mf][1] = *reinterpret_cast<const uint32_t*>(&Ah[rr + gi + 8][kc]);
                ah[mf][2] = *reinterpret_cast<const uint32_t*>(&Ah[rr + gi    ][kc + 8]);
                ah[mf][3] = *reinterpret_cast<const uint32_t*>(&Ah[rr + gi + 8][kc + 8]);
                al[mf][0] = *reinterpret_cast<const uint32_t*>(&Al[rr + gi    ][kc]);
                al[mf][1] = *reinterpret_cast<const uint32_t*>(&Al[rr + gi + 8][kc]);
                al[mf][2] = *reinterpret_cast<const uint32_t*>(&Al[rr + gi    ][kc + 8]);
                al[mf][3] = *reinterpret_cast<const uint32_t*>(&Al[rr + gi + 8][kc + 8]);
            }
            #pragma unroll
            for (int nf = 0; nf < 8; nf++) {
                int nr = wn * 64 + nf * 8 + gi;
                uint32_t bh0 = *reinterpret_cast<const uint32_t*>(&Bh[nr][kc]);
                uint32_t bh1 = *reinterpret_cast<const uint32_t*>(&Bh[nr][kc + 8]);
                uint32_t bl0 = *reinterpret_cast<const uint32_t*>(&Bl[nr][kc]);
                uint32_t bl1 = *reinterpret_cast<const uint32_t*>(&Bl[nr][kc + 8]);
                #pragma unroll
                for (int mf = 0; mf < 2; mf++) {
                    mma_bf16(acc[mf][nf], ah[mf], bh0, bh1);
                    mma_bf16(acc[mf][nf], ah[mf], bl0, bl1);
                    mma_bf16(acc[mf][nf], al[mf], bh0, bh1);
                }
            }
        }
    }
    #pragma unroll
    for (int mf = 0; mf < 2; mf++) {
        #pragma unroll
        for (int nf = 0; nf < 8; nf++) {
            int row0 = bm + wm * 32 + mf * 16 + gi;
            int col  = bn + wn * 64 + nf * 8 + 2 * t;
            *reinterpret_cast<float2*>(C + (size_t)row0 * N + col) =
                make_float2(acc[mf][nf][0], acc[mf][nf][1]);
            *reinterpret_cast<float2*>(C + (size_t)(row0 + 8) * N + col) =
                make_float2(acc[mf][nf][2], acc[mf][nf][3]);
        }
    }
}

// ---------------- per-head LN on q (16 heads) and k (4 groups), bf16 split output ----------------
__global__ __launch_bounds__(128) void qkln_kernel(const float* __restrict__ qs,
                                                   const float* __restrict__ qb,
                                                   const float* __restrict__ ks,
                                                   const float* __restrict__ kb) {
    int row  = blockIdx.x;
    int unit = blockIdx.y * 4 + (threadIdx.x >> 5);   // 0..19
    int lane = threadIdx.x & 31;
    const float *p, *sc, *bi;
    float postmul;
    if (unit < HEADS) {
        p = g_q + (size_t)row * INNER + unit * 64;
        sc = qs; bi = qb; postmul = 0.125f * LOG2E;   // fold Dh^-0.5 and log2(e)
    } else {
        p = g_kv + (size_t)row * KVDIM + (unit - HEADS) * 64;
        sc = ks; bi = kb; postmul = 1.0f;
    }
    float v0 = p[lane], v1 = p[lane + 32];
    float s  = v0 + v1;
    float sq = v0*v0 + v1*v1;
    #pragma unroll
    for (int o = 16; o > 0; o >>= 1) {
        s  += __shfl_xor_sync(0xffffffffu, s,  o);
        sq += __shfl_xor_sync(0xffffffffu, sq, o);
    }
    float mean = s  * (1.f/64.f);
    float var  = sq * (1.f/64.f) - mean*mean;
    float rstd = rsqrtf(var + LN_EPS);
    float r0 = ((v0 - mean)*rstd*sc[lane]      + bi[lane]     ) * postmul;
    float r1 = ((v1 - mean)*rstd*sc[lane + 32] + bi[lane + 32]) * postmul;
    __nv_bfloat16 h0, l0, h1, l1;
    split_bf16(r0, h0, l0);
    split_bf16(r1, h1, l1);
    if (unit < HEADS) {
        size_t base = (size_t)row * INNER + unit * 64;
        g_qh[base + lane] = h0;  g_qh[base + lane + 32] = h1;
        g_ql[base + lane] = l0;  g_ql[base + lane + 32] = l1;
    } else {
        int b = row / SEQ, n = row % SEQ;
        size_t base = ((size_t)(b * GROUPS + (unit - HEADS)) * SEQ + n) * 64;
        g_kh[base + lane] = h0;  g_kh[base + lane + 32] = h1;
        g_kl[base + lane] = l0;  g_kl[base + lane + 32] = l1;
    }
}

// ---------------- V transpose + split: v[n][d] fp32 -> Vt[bg][d][n] bf16 hi/lo ----------------
__global__ __launch_bounds__(256) void vt_kernel() {
    __shared__ float tl[32][33];
    int bg = blockIdx.z;
    int b = bg / GROUPS, g = bg % GROUPS;
    int n0 = blockIdx.x * 32, d0 = blockIdx.y * 32;
    int tx = threadIdx.x & 31, ty = threadIdx.x >> 5;  // 32 x 8
    #pragma unroll
    for (int i = ty; i < 32; i += 8)
        tl[i][tx] = g_kv[(size_t)(b*SEQ + n0 + i) * KVDIM + 256 + g*64 + d0 + tx];
    __syncthreads();
    #pragma unroll
    for (int i = ty; i < 32; i += 8) {
        float v = tl[tx][i];                        // v[n0+tx][d0+i]
        __nv_bfloat16 h, l;
        split_bf16(v, h, l);
        size_t idx = ((size_t)bg * 64 + d0 + i) * SEQ + n0 + tx;
        g_vth[idx] = h;
        g_vtl[idx] = l;
    }
}

// ---------------- warp-MMA flash attention ----------------
// grid (SEQ/128, B*H), 256 threads = 8 warps, warp owns 16 q rows x full kv tile (64).
__global__ __launch_bounds__(256) void attn_mma() {
    __shared__ __nv_bfloat16 Kh[64][72], Kl[64][72], Vh[64][72], Vl[64][72];
    const int tid = threadIdx.x;
    const int warp = tid >> 5, lane = tid & 31;
    const int gi = lane >> 2, t = lane & 3;
    const int by = blockIdx.y;
    const int b = by / HEADS, h = by % HEADS;
    const int bg = b * GROUPS + h / HG;
    const int q0 = blockIdx.x * 128 + warp * 16;

    // load Q fragments (hi/lo) once, keep in regs
    uint32_t qh[4][4], ql[4][4];
    {
        const uint32_t* ph = reinterpret_cast<const uint32_t*>(g_qh);
        const uint32_t* pl = reinterpret_cast<const uint32_t*>(g_ql);
        #pragma unroll
        for (int kf = 0; kf < 4; kf++) {
            int col = kf * 16 + 2 * t;
            size_t i0 = ((size_t)(b*SEQ + q0 + gi    ) * INNER + h*64 + col) >> 1;
            size_t i1 = ((size_t)(b*SEQ + q0 + gi + 8) * INNER + h*64 + col) >> 1;
            qh[kf][0] = ph[i0]; qh[kf][1] = ph[i1]; qh[kf][2] = ph[i0 + 4]; qh[kf][3] = ph[i1 + 4];
            ql[kf][0] = pl[i0]; ql[kf][1] = pl[i1]; ql[kf][2] = pl[i0 + 4]; ql[kf][3] = pl[i1 + 4];
        }
    }

    float o[8][4];
    #pragma unroll
    for (int nd = 0; nd < 8; nd++)
        #pragma unroll
        for (int i = 0; i < 4; i++) o[nd][i] = 0.f;
    float m0 = -1e30f, m1 = -1e30f, l0 = 0.f, l1 = 0.f;

    for (int t0 = 0; t0 < SEQ; t0 += 64) {
        __syncthreads();
        #pragma unroll
        for (int ch = tid; ch < 512; ch += 256) {
            int r = ch >> 3, c = ch & 7;
            const uint4* pkh = reinterpret_cast<const uint4*>(g_kh + ((size_t)bg*SEQ + t0 + r) * 64) + c;
            const uint4* pkl = reinterpret_cast<const uint4*>(g_kl + ((size_t)bg*SEQ + t0 + r) * 64) + c;
            const uint4* pvh = reinterpret_cast<const uint4*>(g_vth + ((size_t)bg*64 + r) * SEQ + t0) + c;
            const uint4* pvl = reinterpret_cast<const uint4*>(g_vtl + ((size_t)bg*64 + r) * SEQ + t0) + c;
            *reinterpret_cast<uint4*>(&Kh[r][c*8]) = *pkh;
            *reinterpret_cast<uint4*>(&Kl[r][c*8]) = *pkl;
            *reinterpret_cast<uint4*>(&Vh[r][c*8]) = *pvh;
            *reinterpret_cast<uint4*>(&Vl[r][c*8]) = *pvl;
        }
        __syncthreads();

        // S = Q K^T (split 3-product)
        float s[8][4];
        #pragma unroll
        for (int nf = 0; nf < 8; nf++)
            #pragma unroll
            for (int i = 0; i < 4; i++) s[nf][i] = 0.f;
        #pragma unroll
        for (int kf = 0; kf < 4; kf++) {
            const int kc = kf * 16 + 2 * t;
            #pragma unroll
            for (int nf = 0; nf < 8; nf++) {
                int nr = nf * 8 + gi;
                uint32_t bh0 = *reinterpret_cast<const uint32_t*>(&Kh[nr][kc]);
                uint32_t bh1 = *reinterpret_cast<const uint32_t*>(&Kh[nr][kc + 8]);
                uint32_t bl0 = *reinterpret_cast<const uint32_t*>(&Kl[nr][kc]);
                uint32_t bl1 = *reinterpret_cast<const uint32_t*>(&Kl[nr][kc + 8]);
                mma_bf16(s[nf], qh[kf], bh0, bh1);
                mma_bf16(s[nf], qh[kf], bl0, bl1);
                mma_bf16(s[nf], ql[kf], bh0, bh1);
            }
        }

        // online softmax (base-2; logits pre-scaled by log2e)
        float mx0 = -1e30f, mx1 = -1e30f;
        #pragma unroll
        for (int nf = 0; nf < 8; nf++) {
            mx0 = fmaxf(mx0, fmaxf(s[nf][0], s[nf][1]));
            mx1 = fmaxf(mx1, fmaxf(s[nf][2], s[nf][3]));
        }
        mx0 = fmaxf(mx0, __shfl_xor_sync(0xffffffffu, mx0, 1));
        mx0 = fmaxf(mx0, __shfl_xor_sync(0xffffffffu, mx0, 2));
        mx1 = fmaxf(mx1, __shfl_xor_sync(0xffffffffu, mx1, 1));
        mx1 = fmaxf(mx1, __shfl_xor_sync(0xffffffffu, mx1, 2));
        float mn0 = fmaxf(m0, mx0), mn1 = fmaxf(m1, mx1);
        float al0 = exp2f(m0 - mn0), al1 = exp2f(m1 - mn1);
        m0 = mn0; m1 = mn1;
        float r0 = 0.f, r1 = 0.f;
        #pragma unroll
        for (int nf = 0; nf < 8; nf++) {
            s[nf][0] = exp2f(s[nf][0] - m0);
            s[nf][1] = exp2f(s[nf][1] - m0);
            s[nf][2] = exp2f(s[nf][2] - m1);
            s[nf][3] = exp2f(s[nf][3] - m1);
            r0 += s[nf][0] + s[nf][1];
            r1 += s[nf][2] + s[nf][3];
        }
        r0 += __shfl_xor_sync(0xffffffffu, r0, 1);
        r0 += __shfl_xor_sync(0xffffffffu, r0, 2);
        r1 += __shfl_xor_sync(0xffffffffu, r1, 1);
        r1 += __shfl_xor_sync(0xffffffffu, r1, 2);
        l0 = l0 * al0 + r0;
        l1 = l1 * al1 + r1;
        #pragma unroll
        for (int nd = 0; nd < 8; nd++) {
            o[nd][0] *= al0; o[nd][1] *= al0;
            o[nd][2] *= al1; o[nd][3] *= al1;
        }

        // P (C-frag) -> A-frag conversion in registers, hi/lo split for precision
        uint32_t pah[4][4], pal[4][4];
        #pragma unroll
        for (int kf = 0; kf < 4; kf++) {
            split_pack2(s[2*kf    ][0], s[2*kf    ][1], pah[kf][0], pal[kf][0]);
            split_pack2(s[2*kf    ][2], s[2*kf    ][3], pah[kf][1], pal[kf][1]);
            split_pack2(s[2*kf + 1][0], s[2*kf + 1][1], pah[kf][2], pal[kf][2]);
            split_pack2(s[2*kf + 1][2], s[2*kf + 1][3], pah[kf][3], pal[kf][3]);
        }
        // O += P @ V (3-product split: Ph*Vh + Ph*Vl + Pl*Vh)
        #pragma unroll
        for (int kf = 0; kf < 4; kf++) {
            const int kc = kf * 16 + 2 * t;
            #pragma unroll
            for (int nd = 0; nd < 8; nd++) {
                int nr = nd * 8 + gi;
                uint32_t vh0 = *reinterpret_cast<const uint32_t*>(&Vh[nr][kc]);
                uint32_t vh1 = *reinterpret_cast<const uint32_t*>(&Vh[nr][kc + 8]);
                uint32_t vl0 = *reinterpret_cast<const uint32_t*>(&Vl[nr][kc]);
                uint32_t vl1 = *reinterpret_cast<const uint32_t*>(&Vl[nr][kc + 8]);
                mma_bf16(o[nd], pah[kf], vh0, vh1);
                mma_bf16(o[nd], pah[kf], vl0, vl1);
                mma_bf16(o[nd], pal[kf], vh0, vh1);
            }
        }
    }

    // epilogue: normalize, split, store bf16 hi/lo
    float inv0 = 1.f / l0, inv1 = 1.f / l1;
    #pragma unroll
    for (int nd = 0; nd < 8; nd++) {
        float v0 = o[nd][0] * inv0, v1 = o[nd][1] * inv0;
        float v2 = o[nd][2] * inv1, v3 = o[nd][3] * inv1;
        __nv_bfloat16 h0, lo0, h1, lo1, h2, lo2, h3, lo3;
        split_bf16(v0, h0, lo0); split_bf16(v1, h1, lo1);
        split_bf16(v2, h2, lo2); split_bf16(v3, h3, lo3);
        size_t i0 = (size_t)(b*SEQ + q0 + gi    ) * INNER + h*64 + nd*8 + 2*t;
        size_t i1 = (size_t)(b*SEQ + q0 + gi + 8) * INNER + h*64 + nd*8 + 2*t;
        *reinterpret_cast<__nv_bfloat162*>(g_oh + i0) = __nv_bfloat162(h0, h1);
        *reinterpret_cast<__nv_bfloat162*>(g_ol + i0) = __nv_bfloat162(lo0, lo1);
        *reinterpret_cast<__nv_bfloat162*>(g_oh + i1) = __nv_bfloat162(h2, h3);
        *reinterpret_cast<__nv_bfloat162*>(g_ol + i1) = __nv_bfloat162(lo2, lo3);
    }
}

extern "C" void kernel_launch(void* const* d_in, const int* in_sizes, int n_in,
                              void* d_out, int out_size) {
    const float* x    = (const float*)d_in[0];
    const float* lns  = (const float*)d_in[1];
    const float* lnb  = (const float*)d_in[2];
    const float* Wq   = (const float*)d_in[3];
    const float* Wkv  = (const float*)d_in[4];
    const float* qns  = (const float*)d_in[5];
    const float* qnb  = (const float*)d_in[6];
    const float* kns  = (const float*)d_in[7];
    const float* knb  = (const float*)d_in[8];
    const float* Wout = (const float*)d_in[9];
    float* out = (float*)d_out;

    void *pxh, *pxl, *pq, *pkv, *poh, *pol;
    void *pwqh, *pwql, *pwkh, *pwkl, *pwoh, *pwol;
    cudaGetSymbolAddress(&pxh, g_xn_hi);  cudaGetSymbolAddress(&pxl, g_xn_lo);
    cudaGetSymbolAddress(&pq,  g_q);      cudaGetSymbolAddress(&pkv, g_kv);
    cudaGetSymbolAddress(&poh, g_oh);     cudaGetSymbolAddress(&pol, g_ol);
    cudaGetSymbolAddress(&pwqh, g_wq_hi); cudaGetSymbolAddress(&pwql, g_wq_lo);
    cudaGetSymbolAddress(&pwkh, g_wkv_hi);cudaGetSymbolAddress(&pwkl, g_wkv_lo);
    cudaGetSymbolAddress(&pwoh, g_wo_hi); cudaGetSymbolAddress(&pwol, g_wo_lo);

    ln_kernel<<<ROWS, 256>>>(x, lns, lnb);
    wconv_kernel<<<dim3(INNER/32, DIM/32), 256>>>(Wq,   (__nv_bfloat16*)pwqh, (__nv_bfloat16*)pwql, DIM, INNER);
    wconv_kernel<<<dim3(KVDIM/32, DIM/32), 256>>>(Wkv,  (__nv_bfloat16*)pwkh, (__nv_bfloat16*)pwkl, DIM, KVDIM);
    wconv_kernel<<<dim3(DIM/32, INNER/32), 256>>>(Wout, (__nv_bfloat16*)pwoh, (__nv_bfloat16*)pwol, INNER, DIM);

    gemm_mma<<<dim3(INNER/128, ROWS/128), 256>>>(
        (const __nv_bfloat16*)pxh, (const __nv_bfloat16*)pxl,
        (const __nv_bfloat16*)pwqh, (const __nv_bfloat16*)pwql,
        (float*)pq, INNER, DIM);
    gemm_mma<<<dim3(KVDIM/128, ROWS/128), 256>>>(
        (const __nv_bfloat16*)pxh, (const __nv_bfloat16*)pxl,
        (const __nv_bfloat16*)pwkh, (const __nv_bfloat16*)pwkl,
        (float*)pkv, KVDIM, DIM);
    qkln_kernel<<<dim3(ROWS, 5), 128>>>(qns, qnb, kns, knb);
    vt_kernel<<<dim3(SEQ/32, 2, BATCH*GROUPS), 256>>>();
    attn_mma<<<dim3(SEQ/128, BATCH*HEADS), 256>>>();
    gemm_mma<<<dim3(DIM/128, ROWS/128), 256>>>(
        (const __nv_bfloat16*)poh, (const __nv_bfloat16*)pol,
        (const __nv_bfloat16*)pwoh, (const __nv_bfloat16*)pwol,
        out, DIM, INNER);
}

// round 5
// speedup vs baseline: 3.5116x; 1.1364x over previous
#include <cuda_runtime.h>
#include <cuda_bf16.h>
#include <cstdint>

#define DIM    1024
#define HEADS  16
#define GROUPS 4
#define HG     (HEADS/GROUPS)
#define DHEAD  64
#define INNER  1024
#define KVDIM  512
#define BATCH  4
#define SEQ    2048
#define ROWS   (BATCH*SEQ)
#define LN_EPS 1e-6f
#define LOG2E  1.44269504088896f

// ---------------- scratch (__device__ globals, allocation-free) ----------------
__device__ __align__(16) __nv_bfloat16 g_xn_hi[ROWS*DIM];
__device__ __align__(16) __nv_bfloat16 g_xn_lo[ROWS*DIM];
__device__ __align__(16) float         g_q [ROWS*INNER];
__device__ __align__(16) float         g_kv[ROWS*KVDIM];
__device__ __align__(16) __nv_bfloat16 g_qh[ROWS*INNER];
__device__ __align__(16) __nv_bfloat16 g_ql[ROWS*INNER];
__device__ __align__(16) __nv_bfloat16 g_kh[BATCH*GROUPS*SEQ*DHEAD];
__device__ __align__(16) __nv_bfloat16 g_kl[BATCH*GROUPS*SEQ*DHEAD];
__device__ __align__(16) __nv_bfloat16 g_vth[BATCH*GROUPS*DHEAD*SEQ];  // [bg][d][n]
__device__ __align__(16) __nv_bfloat16 g_vtl[BATCH*GROUPS*DHEAD*SEQ];
__device__ __align__(16) __nv_bfloat16 g_oh[ROWS*INNER];
__device__ __align__(16) __nv_bfloat16 g_ol[ROWS*INNER];
__device__ __align__(16) __nv_bfloat16 g_wq_hi [INNER*DIM];   // [N,K]
__device__ __align__(16) __nv_bfloat16 g_wq_lo [INNER*DIM];
__device__ __align__(16) __nv_bfloat16 g_wkv_hi[KVDIM*DIM];
__device__ __align__(16) __nv_bfloat16 g_wkv_lo[KVDIM*DIM];
__device__ __align__(16) __nv_bfloat16 g_wo_hi [DIM*INNER];
__device__ __align__(16) __nv_bfloat16 g_wo_lo [DIM*INNER];

// ---------------- helpers ----------------
__device__ __forceinline__ uint32_t smem_u32(const void* p) {
    uint32_t a;
    asm("{ .reg .u64 t; cvta.to.shared.u64 t, %1; cvt.u32.u64 %0, t; }" : "=r"(a) : "l"(p));
    return a;
}
__device__ __forceinline__ void mma_bf16(float c[4], const uint32_t a[4],
                                         uint32_t b0, uint32_t b1) {
    asm volatile(
        "mma.sync.aligned.m16n8k16.row.col.f32.bf16.bf16.f32 "
        "{%0,%1,%2,%3}, {%4,%5,%6,%7}, {%8,%9}, {%0,%1,%2,%3};"
        : "+f"(c[0]), "+f"(c[1]), "+f"(c[2]), "+f"(c[3])
        : "r"(a[0]), "r"(a[1]), "r"(a[2]), "r"(a[3]), "r"(b0), "r"(b1));
}
__device__ __forceinline__ void ldsm_x4(uint32_t addr, uint32_t& r0, uint32_t& r1,
                                        uint32_t& r2, uint32_t& r3) {
    asm volatile("ldmatrix.sync.aligned.m8n8.x4.shared.b16 {%0,%1,%2,%3}, [%4];"
        : "=r"(r0), "=r"(r1), "=r"(r2), "=r"(r3) : "r"(addr));
}
#define CP16(dst, src) \
    asm volatile("cp.async.cg.shared.global [%0], [%1], 16;" :: "r"(dst), "l"(src))
#define CP_COMMIT() asm volatile("cp.async.commit_group;" ::: "memory")
#define CP_WAIT(n)  asm volatile("cp.async.wait_group %0;" :: "n"(n) : "memory")

__device__ __forceinline__ float fexp2(float x) {
    float r;
    asm("ex2.approx.f32 %0, %1;" : "=f"(r) : "f"(x));
    return r;
}
__device__ __forceinline__ void split_bf16(float v, __nv_bfloat16& h, __nv_bfloat16& l) {
    h = __float2bfloat16(v);
    l = __float2bfloat16(v - __bfloat162float(h));
}
__device__ __forceinline__ uint32_t pack2_u32(__nv_bfloat16 a, __nv_bfloat16 b) {
    __nv_bfloat162 p(a, b);
    return *reinterpret_cast<uint32_t*>(&p);
}
__device__ __forceinline__ void split_pack2(float v0, float v1, uint32_t& hw, uint32_t& lw) {
    __nv_bfloat16 h0, l0, h1, l1;
    split_bf16(v0, h0, l0);
    split_bf16(v1, h1, l1);
    hw = pack2_u32(h0, h1);
    lw = pack2_u32(l0, l1);
}

// ---------------- input layernorm, emits bf16 hi/lo split ----------------
__global__ __launch_bounds__(256) void ln_kernel(const float* __restrict__ x,
                                                 const float* __restrict__ sc,
                                                 const float* __restrict__ bi) {
    int row = blockIdx.x;
    int t = threadIdx.x;
    const float4 a = reinterpret_cast<const float4*>(x)[row*(DIM/4) + t];
    float s  = a.x + a.y + a.z + a.w;
    float sq = a.x*a.x + a.y*a.y + a.z*a.z + a.w*a.w;
    #pragma unroll
    for (int o = 16; o > 0; o >>= 1) {
        s  += __shfl_xor_sync(0xffffffffu, s,  o);
        sq += __shfl_xor_sync(0xffffffffu, sq, o);
    }
    __shared__ float ws[8], wq[8];
    if ((t & 31) == 0) { ws[t >> 5] = s; wq[t >> 5] = sq; }
    __syncthreads();
    s = 0.f; sq = 0.f;
    #pragma unroll
    for (int i = 0; i < 8; i++) { s += ws[i]; sq += wq[i]; }
    float mean = s  * (1.f/DIM);
    float var  = sq * (1.f/DIM) - mean*mean;
    float rstd = rsqrtf(var + LN_EPS);
    float4 s4 = reinterpret_cast<const float4*>(sc)[t];
    float4 b4 = reinterpret_cast<const float4*>(bi)[t];
    float v[4];
    v[0] = (a.x - mean)*rstd*s4.x + b4.x;
    v[1] = (a.y - mean)*rstd*s4.y + b4.y;
    v[2] = (a.z - mean)*rstd*s4.z + b4.z;
    v[3] = (a.w - mean)*rstd*s4.w + b4.w;
    __nv_bfloat16 hi[4], lo[4];
    #pragma unroll
    for (int i = 0; i < 4; i++) split_bf16(v[i], hi[i], lo[i]);
    size_t base = (size_t)row * DIM + t * 4;
    *reinterpret_cast<__nv_bfloat162*>(g_xn_hi + base)     = __nv_bfloat162(hi[0], hi[1]);
    *reinterpret_cast<__nv_bfloat162*>(g_xn_hi + base + 2) = __nv_bfloat162(hi[2], hi[3]);
    *reinterpret_cast<__nv_bfloat162*>(g_xn_lo + base)     = __nv_bfloat162(lo[0], lo[1]);
    *reinterpret_cast<__nv_bfloat162*>(g_xn_lo + base + 2) = __nv_bfloat162(lo[2], lo[3]);
}

// ---------------- weight transpose + split: W[K,N] fp32 -> T[N,K] bf16 hi/lo ----------------
__global__ __launch_bounds__(256) void wconv_kernel(const float* __restrict__ W,
                                                    __nv_bfloat16* __restrict__ Thi,
                                                    __nv_bfloat16* __restrict__ Tlo,
                                                    int K, int N) {
    __shared__ float tile[32][33];
    int kb = blockIdx.y * 32, nb = blockIdx.x * 32;
    int tx = threadIdx.x & 31, ty = threadIdx.x >> 5;  // 32 x 8
    #pragma unroll
    for (int i = ty; i < 32; i += 8)
        tile[i][tx] = W[(size_t)(kb + i) * N + nb + tx];
    __syncthreads();
    #pragma unroll
    for (int i = ty; i < 32; i += 8) {
        float v = tile[tx][i];
        __nv_bfloat16 h, l;
        split_bf16(v, h, l);
        size_t idx = (size_t)(nb + i) * K + kb + tx;
        Thi[idx] = h;
        Tlo[idx] = l;
    }
}

// ---------------- warp-MMA split-bf16 GEMM (ldmatrix + cp.async 2-stage) ----------------
// Block tile 128x128, KC=32 per stage, 8 warps (4m x 2n), warp tile 32x64.
// SMEM stage layout: 4 arrays (Ah, Al, Bh, Bl) of [128 rows][80 bytes] (64B data + pad).
#define G_ROWB   80
#define G_ARR_B  (128*G_ROWB)     // 10240
#define G_STAGE  (4*G_ARR_B)      // 40960
#define G_SMEM   (2*G_STAGE)      // 81920

__global__ __launch_bounds__(256, 2) void gemm_mma(const __nv_bfloat16* __restrict__ Ahi,
                                                   const __nv_bfloat16* __restrict__ Alo,
                                                   const __nv_bfloat16* __restrict__ Bhi,
                                                   const __nv_bfloat16* __restrict__ Blo,
                                                   float* __restrict__ C, int N, int K) {
    extern __shared__ char smg[];
    const uint32_t sb = smem_u32(smg);
    const int tid  = threadIdx.x;
    const int warp = tid >> 5, lane = tid & 31;
    const int wm = warp & 3, wn = warp >> 2;
    const int gi = lane >> 2, t = lane & 3;
    const int l7 = lane & 7, l8 = (lane >> 3) & 1, l16 = (lane >> 4) & 1;
    const int bm = blockIdx.y * 128;
    const int bn = blockIdx.x * 128;

    // ldmatrix per-lane row offsets (bytes within a tile array)
    uint32_t aoffA[2], aoffB[4];
    #pragma unroll
    for (int mf = 0; mf < 2; mf++)
        aoffA[mf] = (uint32_t)(wm*32 + mf*16 + l7 + l8*8) * G_ROWB;
    #pragma unroll
    for (int nfp = 0; nfp < 4; nfp++)
        aoffB[nfp] = (uint32_t)(wn*64 + nfp*16 + l7 + l16*8) * G_ROWB;

    float acc[2][8][4];
    #pragma unroll
    for (int mf = 0; mf < 2; mf++)
        #pragma unroll
        for (int nf = 0; nf < 8; nf++)
            #pragma unroll
            for (int i = 0; i < 4; i++) acc[mf][nf][i] = 0.f;

    const int NIT = K / 32;

    // tile loader: 2048 16B chunks per stage, 8 per thread
    auto load_tile = [&](int it, int st) {
        const int k0 = it * 32;
        #pragma unroll
        for (int j = 0; j < 2; j++) {
            int idx = j * 256 + tid;
            int r = idx >> 2, c = idx & 3;
            uint32_t d = sb + st * G_STAGE + (uint32_t)r * G_ROWB + c * 16;
            CP16(d + 0*G_ARR_B, Ahi + (size_t)(bm + r) * K + k0 + c*8);
            CP16(d + 1*G_ARR_B, Alo + (size_t)(bm + r) * K + k0 + c*8);
            CP16(d + 2*G_ARR_B, Bhi + (size_t)(bn + r) * K + k0 + c*8);
            CP16(d + 3*G_ARR_B, Blo + (size_t)(bn + r) * K + k0 + c*8);
        }
    };

    load_tile(0, 0);
    CP_COMMIT();

    for (int it = 0; it < NIT; it++) {
        const int st = it & 1;
        if (it + 1 < NIT) {
            load_tile(it + 1, st ^ 1);
            CP_COMMIT();
            CP_WAIT(1);
        } else {
            CP_WAIT(0);
        }
        __syncthreads();

        const uint32_t tAh = sb + st * G_STAGE;
        const uint32_t tAl = tAh + G_ARR_B;
        const uint32_t tBh = tAh + 2*G_ARR_B;
        const uint32_t tBl = tAh + 3*G_ARR_B;
        #pragma unroll
        for (int ks = 0; ks < 2; ks++) {
            const uint32_t ac = ks*32 + l16*16;
            const uint32_t bc = ks*32 + l8*16;
            uint32_t ah[2][4], al[2][4];
            #pragma unroll
            for (int mf = 0; mf < 2; mf++) {
                ldsm_x4(tAh + aoffA[mf] + ac, ah[mf][0], ah[mf][1], ah[mf][2], ah[mf][3]);
                ldsm_x4(tAl + aoffA[mf] + ac, al[mf][0], al[mf][1], al[mf][2], al[mf][3]);
            }
            #pragma unroll
            for (int nfp = 0; nfp < 4; nfp++) {
                uint32_t h0, h1, h2, h3, p0, p1, p2, p3;
                ldsm_x4(tBh + aoffB[nfp] + bc, h0, h1, h2, h3);
                ldsm_x4(tBl + aoffB[nfp] + bc, p0, p1, p2, p3);
                #pragma unroll
                for (int mf = 0; mf < 2; mf++) {
                    mma_bf16(acc[mf][2*nfp  ], ah[mf], h0, h1);
                    mma_bf16(acc[mf][2*nfp  ], ah[mf], p0, p1);
                    mma_bf16(acc[mf][2*nfp  ], al[mf], h0, h1);
                    mma_bf16(acc[mf][2*nfp+1], ah[mf], h2, h3);
                    mma_bf16(acc[mf][2*nfp+1], ah[mf], p2, p3);
                    mma_bf16(acc[mf][2*nfp+1], al[mf], h2, h3);
                }
            }
        }
        __syncthreads();
    }

    #pragma unroll
    for (int mf = 0; mf < 2; mf++) {
        #pragma unroll
        for (int nf = 0; nf < 8; nf++) {
            int row0 = bm + wm * 32 + mf * 16 + gi;
            int col  = bn + wn * 64 + nf * 8 + 2 * t;
            *reinterpret_cast<float2*>(C + (size_t)row0 * N + col) =
                make_float2(acc[mf][nf][0], acc[mf][nf][1]);
            *reinterpret_cast<float2*>(C + (size_t)(row0 + 8) * N + col) =
                make_float2(acc[mf][nf][2], acc[mf][nf][3]);
        }
    }
}

// ---------------- per-head LN on q (16 heads) and k (4 groups), bf16 split output ----------------
__global__ __launch_bounds__(128) void qkln_kernel(const float* __restrict__ qs,
                                                   const float* __restrict__ qb,
                                                   const float* __restrict__ ks,
                                                   const float* __restrict__ kb) {
    int row  = blockIdx.x;
    int unit = blockIdx.y * 4 + (threadIdx.x >> 5);   // 0..19
    int lane = threadIdx.x & 31;
    const float *p, *sc, *bi;
    float postmul;
    if (unit < HEADS) {
        p = g_q + (size_t)row * INNER + unit * 64;
        sc = qs; bi = qb; postmul = 0.125f * LOG2E;   // fold Dh^-0.5 and log2(e)
    } else {
        p = g_kv + (size_t)row * KVDIM + (unit - HEADS) * 64;
        sc = ks; bi = kb; postmul = 1.0f;
    }
    float v0 = p[lane], v1 = p[lane + 32];
    float s  = v0 + v1;
    float sq = v0*v0 + v1*v1;
    #pragma unroll
    for (int o = 16; o > 0; o >>= 1) {
        s  += __shfl_xor_sync(0xffffffffu, s,  o);
        sq += __shfl_xor_sync(0xffffffffu, sq, o);
    }
    float mean = s  * (1.f/64.f);
    float var  = sq * (1.f/64.f) - mean*mean;
    float rstd = rsqrtf(var + LN_EPS);
    float r0 = ((v0 - mean)*rstd*sc[lane]      + bi[lane]     ) * postmul;
    float r1 = ((v1 - mean)*rstd*sc[lane + 32] + bi[lane + 32]) * postmul;
    __nv_bfloat16 h0, l0, h1, l1;
    split_bf16(r0, h0, l0);
    split_bf16(r1, h1, l1);
    if (unit < HEADS) {
        size_t base = (size_t)row * INNER + unit * 64;
        g_qh[base + lane] = h0;  g_qh[base + lane + 32] = h1;
        g_ql[base + lane] = l0;  g_ql[base + lane + 32] = l1;
    } else {
        int b = row / SEQ, n = row % SEQ;
        size_t base = ((size_t)(b * GROUPS + (unit - HEADS)) * SEQ + n) * 64;
        g_kh[base + lane] = h0;  g_kh[base + lane + 32] = h1;
        g_kl[base + lane] = l0;  g_kl[base + lane + 32] = l1;
    }
}

// ---------------- V transpose + split: v[n][d] fp32 -> Vt[bg][d][n] bf16 hi/lo ----------------
__global__ __launch_bounds__(256) void vt_kernel() {
    __shared__ float tl[32][33];
    int bg = blockIdx.z;
    int b = bg / GROUPS, g = bg % GROUPS;
    int n0 = blockIdx.x * 32, d0 = blockIdx.y * 32;
    int tx = threadIdx.x & 31, ty = threadIdx.x >> 5;  // 32 x 8
    #pragma unroll
    for (int i = ty; i < 32; i += 8)
        tl[i][tx] = g_kv[(size_t)(b*SEQ + n0 + i) * KVDIM + 256 + g*64 + d0 + tx];
    __syncthreads();
    #pragma unroll
    for (int i = ty; i < 32; i += 8) {
        float v = tl[tx][i];                        // v[n0+tx][d0+i]
        __nv_bfloat16 h, l;
        split_bf16(v, h, l);
        size_t idx = ((size_t)bg * 64 + d0 + i) * SEQ + n0 + tx;
        g_vth[idx] = h;
        g_vtl[idx] = l;
    }
}

// ---------------- warp-MMA flash attention (ldmatrix + cp.async 2-stage) ----------------
// grid (SEQ/128, B*H), 256 threads = 8 warps, warp = 16 q rows x 64-wide kv tile.
// SMEM stage: 4 arrays (Kh, Kl, Vh, Vl) of [64 rows][144 bytes] (128B data + pad).
#define A_ROWB   144
#define A_ARR_B  (64*A_ROWB)      // 9216
#define A_STAGE  (4*A_ARR_B)      // 36864
#define A_SMEM   (2*A_STAGE)      // 73728

__global__ __launch_bounds__(256) void attn_mma() {
    extern __shared__ char sma[];
    const uint32_t sb = smem_u32(sma);
    const int tid = threadIdx.x;
    const int warp = tid >> 5, lane = tid & 31;
    const int gi = lane >> 2, t = lane & 3;
    const int l7 = lane & 7, l8 = (lane >> 3) & 1, l16 = (lane >> 4) & 1;
    const int by = blockIdx.y;
    const int b = by / HEADS, h = by % HEADS;
    const int bg = b * GROUPS + h / HG;
    const int q0 = blockIdx.x * 128 + warp * 16;

    // B-operand ldmatrix per-lane row offsets (same for K and V tiles)
    uint32_t aoffB[4];
    #pragma unroll
    for (int nfp = 0; nfp < 4; nfp++)
        aoffB[nfp] = (uint32_t)(nfp*16 + l7 + l16*8) * A_ROWB;

    // load Q fragments (hi/lo) once, keep in regs
    uint32_t qh[4][4], ql[4][4];
    {
        const uint32_t* ph = reinterpret_cast<const uint32_t*>(g_qh);
        const uint32_t* pl = reinterpret_cast<const uint32_t*>(g_ql);
        #pragma unroll
        for (int kf = 0; kf < 4; kf++) {
            int col = kf * 16 + 2 * t;
            size_t i0 = ((size_t)(b*SEQ + q0 + gi    ) * INNER + h*64 + col) >> 1;
            size_t i1 = ((size_t)(b*SEQ + q0 + gi + 8) * INNER + h*64 + col) >> 1;
            qh[kf][0] = ph[i0]; qh[kf][1] = ph[i1]; qh[kf][2] = ph[i0 + 4]; qh[kf][3] = ph[i1 + 4];
            ql[kf][0] = pl[i0]; ql[kf][1] = pl[i1]; ql[kf][2] = pl[i0 + 4]; ql[kf][3] = pl[i1 + 4];
        }
    }

    float o[8][4];
    #pragma unroll
    for (int nd = 0; nd < 8; nd++)
        #pragma unroll
        for (int i = 0; i < 4; i++) o[nd][i] = 0.f;
    float m0 = -1e30f, m1 = -1e30f, l0 = 0.f, l1 = 0.f;

    const __nv_bfloat16* kh_b = g_kh + (size_t)bg * SEQ * 64;
    const __nv_bfloat16* kl_b = g_kl + (size_t)bg * SEQ * 64;
    const __nv_bfloat16* vh_b = g_vth + (size_t)bg * 64 * SEQ;
    const __nv_bfloat16* vl_b = g_vtl + (size_t)bg * 64 * SEQ;

    // tile loader: 2048 16B chunks per stage, 8 per thread
    auto load_tile = [&](int t0, int st) {
        #pragma unroll
        for (int j = 0; j < 2; j++) {
            int idx = j * 256 + tid;
            int r = idx >> 3, c = idx & 7;
            uint32_t d = sb + st * A_STAGE + (uint32_t)r * A_ROWB + c * 16;
            CP16(d + 0*A_ARR_B, kh_b + (size_t)(t0 + r) * 64 + c*8);
            CP16(d + 1*A_ARR_B, kl_b + (size_t)(t0 + r) * 64 + c*8);
            CP16(d + 2*A_ARR_B, vh_b + (size_t)r * SEQ + t0 + c*8);
            CP16(d + 3*A_ARR_B, vl_b + (size_t)r * SEQ + t0 + c*8);
        }
    };

    load_tile(0, 0);
    CP_COMMIT();

    const int NIT = SEQ / 64;
    for (int it = 0; it < NIT; it++) {
        const int st = it & 1;
        if (it + 1 < NIT) {
            load_tile((it + 1) * 64, st ^ 1);
            CP_COMMIT();
            CP_WAIT(1);
        } else {
            CP_WAIT(0);
        }
        __syncthreads();

        const uint32_t tKh = sb + st * A_STAGE;
        const uint32_t tKl = tKh + A_ARR_B;
        const uint32_t tVh = tKh + 2*A_ARR_B;
        const uint32_t tVl = tKh + 3*A_ARR_B;

        // S = Q K^T (split 3-product)
        float s[8][4];
        #pragma unroll
        for (int nf = 0; nf < 8; nf++)
            #pragma unroll
            for (int i = 0; i < 4; i++) s[nf][i] = 0.f;
        #pragma unroll
        for (int kf = 0; kf < 4; kf++) {
            const uint32_t bc = kf*32 + l8*16;
            #pragma unroll
            for (int nfp = 0; nfp < 4; nfp++) {
                uint32_t h0, h1, h2, h3, p0, p1, p2, p3;
                ldsm_x4(tKh + aoffB[nfp] + bc, h0, h1, h2, h3);
                ldsm_x4(tKl + aoffB[nfp] + bc, p0, p1, p2, p3);
                mma_bf16(s[2*nfp  ], qh[kf], h0, h1);
                mma_bf16(s[2*nfp  ], qh[kf], p0, p1);
                mma_bf16(s[2*nfp  ], ql[kf], h0, h1);
                mma_bf16(s[2*nfp+1], qh[kf], h2, h3);
                mma_bf16(s[2*nfp+1], qh[kf], p2, p3);
                mma_bf16(s[2*nfp+1], ql[kf], h2, h3);
            }
        }

        // online softmax (base-2; logits pre-scaled by log2e)
        float mx0 = -1e30f, mx1 = -1e30f;
        #pragma unroll
        for (int nf = 0; nf < 8; nf++) {
            mx0 = fmaxf(mx0, fmaxf(s[nf][0], s[nf][1]));
            mx1 = fmaxf(mx1, fmaxf(s[nf][2], s[nf][3]));
        }
        mx0 = fmaxf(mx0, __shfl_xor_sync(0xffffffffu, mx0, 1));
        mx0 = fmaxf(mx0, __shfl_xor_sync(0xffffffffu, mx0, 2));
        mx1 = fmaxf(mx1, __shfl_xor_sync(0xffffffffu, mx1, 1));
        mx1 = fmaxf(mx1, __shfl_xor_sync(0xffffffffu, mx1, 2));
        float mn0 = fmaxf(m0, mx0), mn1 = fmaxf(m1, mx1);
        float al0 = fexp2(m0 - mn0), al1 = fexp2(m1 - mn1);
        m0 = mn0; m1 = mn1;
        float r0 = 0.f, r1 = 0.f;
        #pragma unroll
        for (int nf = 0; nf < 8; nf++) {
            s[nf][0] = fexp2(s[nf][0] - m0);
            s[nf][1] = fexp2(s[nf][1] - m0);
            s[nf][2] = fexp2(s[nf][2] - m1);
            s[nf][3] = fexp2(s[nf][3] - m1);
            r0 += s[nf][0] + s[nf][1];
            r1 += s[nf][2] + s[nf][3];
        }
        r0 += __shfl_xor_sync(0xffffffffu, r0, 1);
        r0 += __shfl_xor_sync(0xffffffffu, r0, 2);
        r1 += __shfl_xor_sync(0xffffffffu, r1, 1);
        r1 += __shfl_xor_sync(0xffffffffu, r1, 2);
        l0 = l0 * al0 + r0;
        l1 = l1 * al1 + r1;
        #pragma unroll
        for (int nd = 0; nd < 8; nd++) {
            o[nd][0] *= al0; o[nd][1] *= al0;
            o[nd][2] *= al1; o[nd][3] *= al1;
        }

        // P (C-frag) -> A-frag conversion in registers, hi/lo split
        uint32_t pah[4][4], pal[4][4];
        #pragma unroll
        for (int kf = 0; kf < 4; kf++) {
            split_pack2(s[2*kf    ][0], s[2*kf    ][1], pah[kf][0], pal[kf][0]);
            split_pack2(s[2*kf    ][2], s[2*kf    ][3], pah[kf][1], pal[kf][1]);
            split_pack2(s[2*kf + 1][0], s[2*kf + 1][1], pah[kf][2], pal[kf][2]);
            split_pack2(s[2*kf + 1][2], s[2*kf + 1][3], pah[kf][3], pal[kf][3]);
        }
        // O += P @ V (3-product split)
        #pragma unroll
        for (int kf = 0; kf < 4; kf++) {
            const uint32_t bc = kf*32 + l8*16;
            #pragma unroll
            for (int ndp = 0; ndp < 4; ndp++) {
                uint32_t h0, h1, h2, h3, p0, p1, p2, p3;
                ldsm_x4(tVh + aoffB[ndp] + bc, h0, h1, h2, h3);
                ldsm_x4(tVl + aoffB[ndp] + bc, p0, p1, p2, p3);
                mma_bf16(o[2*ndp  ], pah[kf], h0, h1);
                mma_bf16(o[2*ndp  ], pah[kf], p0, p1);
                mma_bf16(o[2*ndp  ], pal[kf], h0, h1);
                mma_bf16(o[2*ndp+1], pah[kf], h2, h3);
                mma_bf16(o[2*ndp+1], pah[kf], p2, p3);
                mma_bf16(o[2*ndp+1], pal[kf], h2, h3);
            }
        }
        __syncthreads();
    }

    // epilogue: normalize, split, store bf16 hi/lo
    float inv0 = 1.f / l0, inv1 = 1.f / l1;
    #pragma unroll
    for (int nd = 0; nd < 8; nd++) {
        float v0 = o[nd][0] * inv0, v1 = o[nd][1] * inv0;
        float v2 = o[nd][2] * inv1, v3 = o[nd][3] * inv1;
        __nv_bfloat16 h0, lo0, h1, lo1, h2, lo2, h3, lo3;
        split_bf16(v0, h0, lo0); split_bf16(v1, h1, lo1);
        split_bf16(v2, h2, lo2); split_bf16(v3, h3, lo3);
        size_t i0 = (size_t)(b*SEQ + q0 + gi    ) * INNER + h*64 + nd*8 + 2*t;
        size_t i1 = (size_t)(b*SEQ + q0 + gi + 8) * INNER + h*64 + nd*8 + 2*t;
        *reinterpret_cast<__nv_bfloat162*>(g_oh + i0) = __nv_bfloat162(h0, h1);
        *reinterpret_cast<__nv_bfloat162*>(g_ol + i0) = __nv_bfloat162(lo0, lo1);
        *reinterpret_cast<__nv_bfloat162*>(g_oh + i1) = __nv_bfloat162(h2, h3);
        *reinterpret_cast<__nv_bfloat162*>(g_ol + i1) = __nv_bfloat162(lo2, lo3);
    }
}

extern "C" void kernel_launch(void* const* d_in, const int* in_sizes, int n_in,
                              void* d_out, int out_size) {
    const float* x    = (const float*)d_in[0];
    const float* lns  = (const float*)d_in[1];
    const float* lnb  = (const float*)d_in[2];
    const float* Wq   = (const float*)d_in[3];
    const float* Wkv  = (const float*)d_in[4];
    const float* qns  = (const float*)d_in[5];
    const float* qnb  = (const float*)d_in[6];
    const float* kns  = (const float*)d_in[7];
    const float* knb  = (const float*)d_in[8];
    const float* Wout = (const float*)d_in[9];
    float* out = (float*)d_out;

    void *pxh, *pxl, *pq, *pkv;
    void *poh, *pol, *pwqh, *pwql, *pwkh, *pwkl, *pwoh, *pwol;
    cudaGetSymbolAddress(&pxh, g_xn_hi);  cudaGetSymbolAddress(&pxl, g_xn_lo);
    cudaGetSymbolAddress(&pq,  g_q);      cudaGetSymbolAddress(&pkv, g_kv);
    cudaGetSymbolAddress(&poh, g_oh);     cudaGetSymbolAddress(&pol, g_ol);
    cudaGetSymbolAddress(&pwqh, g_wq_hi); cudaGetSymbolAddress(&pwql, g_wq_lo);
    cudaGetSymbolAddress(&pwkh, g_wkv_hi);cudaGetSymbolAddress(&pwkl, g_wkv_lo);
    cudaGetSymbolAddress(&pwoh, g_wo_hi); cudaGetSymbolAddress(&pwol, g_wo_lo);

    cudaFuncSetAttribute(gemm_mma, cudaFuncAttributeMaxDynamicSharedMemorySize, G_SMEM);
    cudaFuncSetAttribute(attn_mma, cudaFuncAttributeMaxDynamicSharedMemorySize, A_SMEM);

    ln_kernel<<<ROWS, 256>>>(x, lns, lnb);
    wconv_kernel<<<dim3(INNER/32, DIM/32), 256>>>(Wq,   (__nv_bfloat16*)pwqh, (__nv_bfloat16*)pwql, DIM, INNER);
    wconv_kernel<<<dim3(KVDIM/32, DIM/32), 256>>>(Wkv,  (__nv_bfloat16*)pwkh, (__nv_bfloat16*)pwkl, DIM, KVDIM);
    wconv_kernel<<<dim3(DIM/32, INNER/32), 256>>>(Wout, (__nv_bfloat16*)pwoh, (__nv_bfloat16*)pwol, INNER, DIM);

    gemm_mma<<<dim3(INNER/128, ROWS/128), 256, G_SMEM>>>(
        (const __nv_bfloat16*)pxh, (const __nv_bfloat16*)pxl,
        (const __nv_bfloat16*)pwqh, (const __nv_bfloat16*)pwql,
        (float*)pq, INNER, DIM);
    gemm_mma<<<dim3(KVDIM/128, ROWS/128), 256, G_SMEM>>>(
        (const __nv_bfloat16*)pxh, (const __nv_bfloat16*)pxl,
        (const __nv_bfloat16*)pwkh, (const __nv_bfloat16*)pwkl,
        (float*)pkv, KVDIM, DIM);
    qkln_kernel<<<dim3(ROWS, 5), 128>>>(qns, qnb, kns, knb);
    vt_kernel<<<dim3(SEQ/32, 2, BATCH*GROUPS), 256>>>();
    attn_mma<<<dim3(SEQ/128, BATCH*HEADS), 256, A_SMEM>>>();
    gemm_mma<<<dim3(DIM/128, ROWS/128), 256, G_SMEM>>>(
        (const __nv_bfloat16*)poh, (const __nv_bfloat16*)pol,
        (const __nv_bfloat16*)pwoh, (const __nv_bfloat16*)pwol,
        out, DIM, INNER);
}